// round 3
// baseline (speedup 1.0000x reference)
#include <cuda_runtime.h>
#include <math.h>

#define Bn 16
#define Hn 64
#define Wn 64
#define Cn 256
#define Nn 8
#define Dn 32
#define NROW (Bn*Hn*Wn)   // 65536

// ---------------- scratch (device globals; no allocation) ----------------
__device__ float g_q[NROW*Cn];
__device__ float g_k[NROW*Cn];
__device__ float g_v[NROW*Cn];
__device__ float g_lepe[NROW*Cn];
__device__ float g_pre[NROW*Cn];
__device__ float g_qkw[Bn*Hn*Nn*64*64];      // [b][h][n][i=w][j=w]
__device__ float g_vw[Bn*Hn*Nn*64*32];       // [b][h][n][w][d]
__device__ float g_vh2[Bn*Wn*Nn*64*32];      // [b][w][n][h][d]
__device__ float g_da[Bn*Hn*Nn*Wn];          // [b][h][n][w]
__device__ float g_db[Bn*Wn*Nn*Hn];          // [b][w][n][h]

// ---------------- GEMM: out[r,c] = (sum_k A[r,k]*Wt[c,k] + bias[c]) * scale
__global__ __launch_bounds__(256) void gemm_bias_kernel(
    const float* __restrict__ Aext, const float* __restrict__ Wt,
    const float* __restrict__ bias, float* dout,
    int src_sel, int dst_sel, float scale)
{
    const float* A = (src_sel == 0) ? Aext : g_pre;
    float* outp = (dst_sel == 0) ? g_q : (dst_sel == 1) ? g_k
                : (dst_sel == 2) ? g_v : dout;

    __shared__ float As[16][68];
    __shared__ float Bs[16][68];
    int tid = threadIdx.x;
    int row0 = blockIdx.x * 64;
    int col0 = blockIdx.y * 64;
    int lm = tid >> 2;
    int lk = (tid & 3) << 2;
    int tx = tid & 15, ty = tid >> 4;

    float acc[4][4];
#pragma unroll
    for (int i = 0; i < 4; i++)
#pragma unroll
        for (int j = 0; j < 4; j++) acc[i][j] = 0.f;

    for (int k0 = 0; k0 < 256; k0 += 16) {
        float4 a = *(const float4*)(A  + (row0 + lm) * 256 + k0 + lk);
        float4 b = *(const float4*)(Wt + (col0 + lm) * 256 + k0 + lk);
        As[lk + 0][lm] = a.x; As[lk + 1][lm] = a.y; As[lk + 2][lm] = a.z; As[lk + 3][lm] = a.w;
        Bs[lk + 0][lm] = b.x; Bs[lk + 1][lm] = b.y; Bs[lk + 2][lm] = b.z; Bs[lk + 3][lm] = b.w;
        __syncthreads();
#pragma unroll
        for (int kk = 0; kk < 16; kk++) {
            float4 av = *(const float4*)&As[kk][ty << 2];
            float4 bv = *(const float4*)&Bs[kk][tx << 2];
            float ar[4] = {av.x, av.y, av.z, av.w};
            float br[4] = {bv.x, bv.y, bv.z, bv.w};
#pragma unroll
            for (int i = 0; i < 4; i++)
#pragma unroll
                for (int j = 0; j < 4; j++) acc[i][j] += ar[i] * br[j];
        }
        __syncthreads();
    }
#pragma unroll
    for (int i = 0; i < 4; i++) {
        int r = row0 + (ty << 2) + i;
#pragma unroll
        for (int j = 0; j < 4; j++) {
            int c = col0 + (tx << 2) + j;
            outp[r * 256 + c] = (acc[i][j] + bias[c]) * scale;
        }
    }
}

// ---------------- RoPE (in-place on g_q/g_k) + dt -> da/db ----------------
__device__ __forceinline__ float softplusf(float a) {
    return (a > 20.f) ? a : log1pf(expf(a));
}

__global__ __launch_bounds__(256) void rope_dt_kernel(
    const float* __restrict__ x, const float* __restrict__ sinp,
    const float* __restrict__ cosp, const float* __restrict__ dtw,
    const float* __restrict__ dtb, const float* __restrict__ Alog)
{
    int r = blockIdx.x;          // (b*64 + h)*64 + w
    int w = r & 63;
    int h = (r >> 6) & 63;
    int b = r >> 12;
    int c = threadIdx.x;
    int n = c >> 5, d = c & 31;

    float sv = sinp[(h * 64 + w) * 32 + d];
    float cv = cosp[(h * 64 + w) * 32 + d];

    float qv = g_q[r * 256 + c];
    float kv = g_k[r * 256 + c];
    float qp = __shfl_xor_sync(0xffffffffu, qv, 1);
    float kp = __shfl_xor_sync(0xffffffffu, kv, 1);
    float qr = (d & 1) ? qp : -qp;   // rot[2i] = -x[2i+1]; rot[2i+1] = x[2i]
    float kr = (d & 1) ? kp : -kp;
    g_q[r * 256 + c] = qv * cv + qr * sv;
    g_k[r * 256 + c] = kv * cv + kr * sv;

    float xv = x[r * 256 + c];
    float t0 = xv * dtw[d];
    float t1 = xv * dtw[32 + d];
#pragma unroll
    for (int off = 16; off; off >>= 1) {
        t0 += __shfl_down_sync(0xffffffffu, t0, off);
        t1 += __shfl_down_sync(0xffffffffu, t1, off);
    }
    if (d == 0) {
        float bias = dtb[n];
        float Aa = -expf(Alog[n]);
        float da = softplusf(t0 + bias) * Aa;
        float db = softplusf(t1 + bias) * Aa;
        g_da[((b * 64 + h) * 8 + n) * 64 + w] = da;
        g_db[((b * 64 + w) * 8 + n) * 64 + h] = db;
    }
}

// ---------------- LePE depthwise 5x5 conv ----------------
__global__ __launch_bounds__(256) void lepe_kernel(
    const float* __restrict__ lw, const float* __restrict__ lb)
{
    int r = blockIdx.x;
    int w = r & 63, h = (r >> 6) & 63, b = r >> 12;
    int c = threadIdx.x;
    float acc = lb[c];
#pragma unroll
    for (int ki = 0; ki < 5; ki++) {
        int hh = h + ki - 2;
        if ((unsigned)hh >= 64u) continue;
#pragma unroll
        for (int kj = 0; kj < 5; kj++) {
            int ww = w + kj - 2;
            if ((unsigned)ww >= 64u) continue;
            acc += __ldg(&g_v[((b * 64 + hh) * 64 + ww) * 256 + c]) * lw[(ki * 5 + kj) * 256 + c];
        }
    }
    g_lepe[r * 256 + c] = acc;
}

// ---------------- attention along W: qk_w (stored) + v_w ----------------
__global__ __launch_bounds__(256) void attn_w_kernel(void)
{
    int blk = blockIdx.x;                 // (b*64 + h)*8 + n
    int n = blk & 7;
    int h = (blk >> 3) & 63;
    int b = blk >> 9;
    __shared__ float qs[64][33];
    __shared__ float ks[64][33];
    __shared__ float S[64][65];
    __shared__ float cs[64];
    int tid = threadIdx.x;
    int qbase = ((b * 64 + h) * 64) * 256 + n * 32;   // + i*256 + d

    for (int e = tid; e < 2048; e += 256) {
        int i = e >> 5, d = e & 31;
        qs[i][d] = g_q[qbase + i * 256 + d];
        ks[i][d] = g_k[qbase + i * 256 + d];
    }
    if (tid == 0) {
        float run = 0.f;
        const float* dap = g_da + blk * 64;
        for (int j = 0; j < 64; j++) { run += dap[j]; cs[j] = run; }
    }
    __syncthreads();

    // S = Q K^T + segsum mask
    int i0 = (tid >> 4) << 2;
    int j0 = (tid & 15) << 2;
    float s4[4][4];
#pragma unroll
    for (int a = 0; a < 4; a++)
#pragma unroll
        for (int c2 = 0; c2 < 4; c2++) s4[a][c2] = 0.f;
#pragma unroll 4
    for (int d = 0; d < 32; d++) {
        float qv[4], kv[4];
#pragma unroll
        for (int a = 0; a < 4; a++) qv[a] = qs[i0 + a][d];
#pragma unroll
        for (int a = 0; a < 4; a++) kv[a] = ks[j0 + a][d];
#pragma unroll
        for (int a = 0; a < 4; a++)
#pragma unroll
            for (int c2 = 0; c2 < 4; c2++) s4[a][c2] += qv[a] * kv[c2];
    }
#pragma unroll
    for (int a = 0; a < 4; a++) {
        int i = i0 + a;
#pragma unroll
        for (int c2 = 0; c2 < 4; c2++) {
            int j = j0 + c2;
            float diff = cs[i] - cs[j];
            S[i][j] = s4[a][c2] + ((i >= j) ? diff : -diff);
        }
    }
    __syncthreads();

    // softmax rows
    int wp = tid >> 5, lane = tid & 31;
    for (int rr = 0; rr < 8; rr++) {
        int i = wp * 8 + rr;
        float v0 = S[i][lane], v1 = S[i][lane + 32];
        float m = fmaxf(v0, v1);
#pragma unroll
        for (int off = 16; off; off >>= 1) m = fmaxf(m, __shfl_xor_sync(0xffffffffu, m, off));
        float e0 = expf(v0 - m), e1 = expf(v1 - m);
        float s = e0 + e1;
#pragma unroll
        for (int off = 16; off; off >>= 1) s += __shfl_xor_sync(0xffffffffu, s, off);
        float inv = 1.f / s;
        S[i][lane] = e0 * inv;
        S[i][lane + 32] = e1 * inv;
    }
    __syncthreads();

    // store qk_w
    float* qp = g_qkw + blk * 4096;
    for (int e = tid; e < 4096; e += 256) qp[e] = S[e >> 6][e & 63];

    // reload V into qs
    for (int e = tid; e < 2048; e += 256) {
        int i = e >> 5, d = e & 31;
        qs[i][d] = g_v[qbase + i * 256 + d];
    }
    __syncthreads();

    // v_w = P @ V
    int d = tid & 31;
    int ib = tid >> 5;
    float acc[8];
#pragma unroll
    for (int a = 0; a < 8; a++) acc[a] = 0.f;
    for (int j = 0; j < 64; j++) {
        float vv = qs[j][d];
#pragma unroll
        for (int a = 0; a < 8; a++) acc[a] += S[ib * 8 + a][j] * vv;
    }
    float* vwp = g_vw + blk * 2048;
#pragma unroll
    for (int a = 0; a < 8; a++) vwp[(ib * 8 + a) * 32 + d] = acc[a];
}

// ---- attention along H: qk_h in SMEM only; emits v_h2 and 0.5*out1 ----
__global__ __launch_bounds__(256) void attn_h_kernel(void)
{
    int blk = blockIdx.x;                 // (b*64 + x)*8 + n
    int n = blk & 7;
    int x = (blk >> 3) & 63;
    int b = blk >> 9;
    __shared__ float qs[64][33];
    __shared__ float ks[64][33];
    __shared__ float S[64][65];
    __shared__ float cs[64];
    int tid = threadIdx.x;
    int qbase = (b * 64 * 64 + x) * 256 + n * 32;     // + i*16384 + d

    for (int e = tid; e < 2048; e += 256) {
        int i = e >> 5, d = e & 31;
        qs[i][d] = g_q[qbase + i * 16384 + d];
        ks[i][d] = g_k[qbase + i * 16384 + d];
    }
    if (tid == 0) {
        float run = 0.f;
        const float* dbp = g_db + blk * 64;
        for (int j = 0; j < 64; j++) { run += dbp[j]; cs[j] = run; }
    }
    __syncthreads();

    int i0 = (tid >> 4) << 2;
    int j0 = (tid & 15) << 2;
    float s4[4][4];
#pragma unroll
    for (int a = 0; a < 4; a++)
#pragma unroll
        for (int c2 = 0; c2 < 4; c2++) s4[a][c2] = 0.f;
#pragma unroll 4
    for (int d = 0; d < 32; d++) {
        float qv[4], kv[4];
#pragma unroll
        for (int a = 0; a < 4; a++) qv[a] = qs[i0 + a][d];
#pragma unroll
        for (int a = 0; a < 4; a++) kv[a] = ks[j0 + a][d];
#pragma unroll
        for (int a = 0; a < 4; a++)
#pragma unroll
            for (int c2 = 0; c2 < 4; c2++) s4[a][c2] += qv[a] * kv[c2];
    }
#pragma unroll
    for (int a = 0; a < 4; a++) {
        int i = i0 + a;
#pragma unroll
        for (int c2 = 0; c2 < 4; c2++) {
            int j = j0 + c2;
            float diff = cs[i] - cs[j];
            S[i][j] = s4[a][c2] + ((i >= j) ? diff : -diff);
        }
    }
    __syncthreads();

    int wp = tid >> 5, lane = tid & 31;
    for (int rr = 0; rr < 8; rr++) {
        int i = wp * 8 + rr;
        float v0 = S[i][lane], v1 = S[i][lane + 32];
        float m = fmaxf(v0, v1);
#pragma unroll
        for (int off = 16; off; off >>= 1) m = fmaxf(m, __shfl_xor_sync(0xffffffffu, m, off));
        float e0 = expf(v0 - m), e1 = expf(v1 - m);
        float s = e0 + e1;
#pragma unroll
        for (int off = 16; off; off >>= 1) s += __shfl_xor_sync(0xffffffffu, s, off);
        float inv = 1.f / s;
        S[i][lane] = e0 * inv;
        S[i][lane + 32] = e1 * inv;
    }
    __syncthreads();

    // load vh (cols of V) into qs, v_w rows into ks
    for (int e = tid; e < 2048; e += 256) {
        int i = e >> 5, d = e & 31;
        qs[i][d] = g_v[qbase + i * 16384 + d];
        ks[i][d] = g_vw[((b * 64 + i) * 8 + n) * 2048 + x * 32 + d];
    }
    __syncthreads();

    int d = tid & 31;
    int ib = tid >> 5;
    float acc1[8], acc2[8];
#pragma unroll
    for (int a = 0; a < 8; a++) { acc1[a] = 0.f; acc2[a] = 0.f; }
    for (int j = 0; j < 64; j++) {
        float vv1 = qs[j][d];
        float vv2 = ks[j][d];
#pragma unroll
        for (int a = 0; a < 8; a++) {
            float p = S[ib * 8 + a][j];
            acc1[a] += p * vv1;
            acc2[a] += p * vv2;
        }
    }
    float* v2p = g_vh2 + blk * 2048;
#pragma unroll
    for (int a = 0; a < 8; a++) {
        int i = ib * 8 + a;
        v2p[i * 32 + d] = acc1[a];                               // v_h2[b][x][n][h=i][d]
        g_pre[((b * 64 + i) * 64 + x) * 256 + n * 32 + d] = 0.5f * acc2[a];  // 0.5*out1
    }
}

// ---------------- out2: pre += 0.5*(qk_w @ v_h2) + lepe ----------------
__global__ __launch_bounds__(256) void out2_kernel(void)
{
    int blk = blockIdx.x;                 // (b*64 + y)*8 + n, y = h
    int n = blk & 7;
    int y = (blk >> 3) & 63;
    int b = blk >> 9;
    __shared__ float S[64][65];
    __shared__ float vs[64][33];
    int tid = threadIdx.x;

    const float* qp = g_qkw + blk * 4096;
    for (int e = tid; e < 4096; e += 256) S[e >> 6][e & 63] = qp[e];
    for (int e = tid; e < 2048; e += 256) {
        int j = e >> 5, d = e & 31;
        vs[j][d] = g_vh2[((b * 64 + j) * 8 + n) * 2048 + y * 32 + d];
    }
    __syncthreads();

    int d = tid & 31;
    int ib = tid >> 5;
    float acc[8];
#pragma unroll
    for (int a = 0; a < 8; a++) acc[a] = 0.f;
    for (int j = 0; j < 64; j++) {
        float vv = vs[j][d];
#pragma unroll
        for (int a = 0; a < 8; a++) acc[a] += S[ib * 8 + a][j] * vv;
    }
#pragma unroll
    for (int a = 0; a < 8; a++) {
        int i = ib * 8 + a;                                   // w index
        int addr = ((b * 64 + y) * 64 + i) * 256 + n * 32 + d;
        g_pre[addr] = g_pre[addr] + 0.5f * acc[a] + g_lepe[addr];
    }
}

// ---------------- launch ----------------
extern "C" void kernel_launch(void* const* d_in, const int* in_sizes, int n_in,
                              void* d_out, int out_size)
{
    const float* x    = (const float*)d_in[0];
    // d_in[1] sin, d_in[2] cos
    const float* sinp = (const float*)d_in[1];
    const float* cosp = (const float*)d_in[2];
    const float* Wq   = (const float*)d_in[3];
    const float* bq   = (const float*)d_in[4];
    const float* Wk   = (const float*)d_in[5];
    const float* bk   = (const float*)d_in[6];
    const float* Wv   = (const float*)d_in[7];
    const float* bv   = (const float*)d_in[8];
    const float* Wo   = (const float*)d_in[9];
    const float* bo   = (const float*)d_in[10];
    const float* lw   = (const float*)d_in[11];
    const float* lb   = (const float*)d_in[12];
    const float* dtw  = (const float*)d_in[13];
    const float* dtb  = (const float*)d_in[14];
    const float* Alog = (const float*)d_in[15];
    float* out = (float*)d_out;

    const float scaling = 0.17677669529663687f;   // 32^-0.5
    dim3 gg(NROW / 64, 4);

    gemm_bias_kernel<<<gg, 256>>>(x, Wq, bq, nullptr, 0, 0, 1.0f);       // q
    gemm_bias_kernel<<<gg, 256>>>(x, Wk, bk, nullptr, 0, 1, scaling);    // k (scaled)
    gemm_bias_kernel<<<gg, 256>>>(x, Wv, bv, nullptr, 0, 2, 1.0f);       // v

    rope_dt_kernel<<<NROW, 256>>>(x, sinp, cosp, dtw, dtb, Alog);
    lepe_kernel<<<NROW, 256>>>(lw, lb);

    attn_w_kernel<<<Bn * Hn * Nn, 256>>>();
    attn_h_kernel<<<Bn * Wn * Nn, 256>>>();
    out2_kernel<<<Bn * Hn * Nn, 256>>>();

    gemm_bias_kernel<<<gg, 256>>>(nullptr, Wo, bo, out, 1, 3, 1.0f);     // final proj
}

// round 5
// speedup vs baseline: 1.3814x; 1.3814x over previous
#include <cuda_runtime.h>
#include <cuda_bf16.h>
#include <math.h>
#include <stdint.h>

#define Bn 16
#define Hn 64
#define Wn 64
#define Cn 256
#define Nn 8
#define Dn 32
#define NROW (Bn*Hn*Wn)   // 65536

// ---------------- scratch (device globals; no allocation) ----------------
__device__ float g_q[NROW*Cn];
__device__ float g_k[NROW*Cn];
__device__ float g_v[NROW*Cn];
__device__ float g_lepe[NROW*Cn];
__device__ float g_pre[NROW*Cn];
__device__ float g_qkw[Bn*Hn*Nn*64*64];      // [b][h][n][i=w][j=w]
__device__ float g_vw[Bn*Hn*Nn*64*32];       // [b][h][n][w][d]
__device__ float g_vh2[Bn*Wn*Nn*64*32];      // [b][w][n][h][d]
__device__ float g_da[Bn*Hn*Nn*Wn];          // [b][h][n][w]
__device__ float g_db[Bn*Wn*Nn*Hn];          // [b][w][n][h]

// bf16 hi/lo split buffers for tensor-core GEMMs
__device__ __nv_bfloat16 g_ahi[NROW*Cn];
__device__ __nv_bfloat16 g_alo[NROW*Cn];
__device__ __nv_bfloat16 g_whi[Cn*Cn];
__device__ __nv_bfloat16 g_wlo[Cn*Cn];

// ---------------- helpers ----------------
__device__ __forceinline__ uint32_t smem_u32(const void* p) {
    uint32_t a;
    asm("{ .reg .u64 t; cvta.to.shared.u64 t, %1; cvt.u32.u64 %0, t; }"
        : "=r"(a) : "l"(p));
    return a;
}

__device__ __forceinline__ uint32_t pack_bf2(float a, float b) {
    return (uint32_t)__bfloat16_as_ushort(__float2bfloat16_rn(a))
         | ((uint32_t)__bfloat16_as_ushort(__float2bfloat16_rn(b)) << 16);
}

// split float4 -> 4 bf16 hi (uint2) and 4 bf16 lo (uint2)
__device__ __forceinline__ void split4(float4 a, uint2& hv, uint2& lv) {
    float h0 = __bfloat162float(__float2bfloat16_rn(a.x));
    float h1 = __bfloat162float(__float2bfloat16_rn(a.y));
    float h2 = __bfloat162float(__float2bfloat16_rn(a.z));
    float h3 = __bfloat162float(__float2bfloat16_rn(a.w));
    hv.x = pack_bf2(a.x, a.y);
    hv.y = pack_bf2(a.z, a.w);
    lv.x = pack_bf2(a.x - h0, a.y - h1);
    lv.y = pack_bf2(a.z - h2, a.w - h3);
}

// ------------- conversion passes: fp32 -> bf16 hi/lo -------------
__global__ __launch_bounds__(256) void convA_kernel(const float* __restrict__ srcExt, int sel)
{
    const float* src = (sel == 0) ? srcExt : g_pre;
    size_t i = ((size_t)blockIdx.x * 256 + threadIdx.x) * 4;
    float4 v = *(const float4*)(src + i);
    uint2 hv, lv; split4(v, hv, lv);
    *(uint2*)(g_ahi + i) = hv;
    *(uint2*)(g_alo + i) = lv;
}

__global__ __launch_bounds__(256) void convW_kernel(const float* __restrict__ src)
{
    size_t i = ((size_t)blockIdx.x * 256 + threadIdx.x) * 4;
    float4 v = *(const float4*)(src + i);
    uint2 hv, lv; split4(v, hv, lv);
    *(uint2*)(g_whi + i) = hv;
    *(uint2*)(g_wlo + i) = lv;
}

// ------------- tensor-core GEMM via mma.sync (bf16, fp32 acc, 3-term emu) -------------
// out[r,c] = (sum_k A[r,k]*W[c,k] + bias[c]) * scale
// CTA: 128 rows x 128 cols. 8 warps in 2(m) x 4(n). BK=32, 8 chunks.
#define GP 40   // smem pitch (bf16 elems)

__device__ __forceinline__ void ldm4(uint32_t addr, uint32_t& r0, uint32_t& r1,
                                     uint32_t& r2, uint32_t& r3) {
    asm volatile("ldmatrix.sync.aligned.m8n8.x4.shared.b16 {%0,%1,%2,%3}, [%4];"
                 : "=r"(r0), "=r"(r1), "=r"(r2), "=r"(r3) : "r"(addr));
}

__device__ __forceinline__ void mma16816(float* d, const uint32_t* a,
                                         uint32_t b0, uint32_t b1) {
    asm volatile("mma.sync.aligned.m16n8k16.row.col.f32.bf16.bf16.f32 "
                 "{%0,%1,%2,%3}, {%4,%5,%6,%7}, {%8,%9}, {%0,%1,%2,%3};"
                 : "+f"(d[0]), "+f"(d[1]), "+f"(d[2]), "+f"(d[3])
                 : "r"(a[0]), "r"(a[1]), "r"(a[2]), "r"(a[3]), "r"(b0), "r"(b1));
}

__global__ __launch_bounds__(256) void gemm_mma_kernel(
    const float* __restrict__ bias, float* __restrict__ dout,
    int dst_sel, float scale)
{
    float* outp = (dst_sel == 0) ? g_q : (dst_sel == 1) ? g_k
                : (dst_sel == 2) ? g_v : dout;

    __shared__ __align__(16) __nv_bfloat16 sAhi[128 * GP];
    __shared__ __align__(16) __nv_bfloat16 sAlo[128 * GP];
    __shared__ __align__(16) __nv_bfloat16 sBhi[128 * GP];
    __shared__ __align__(16) __nv_bfloat16 sBlo[128 * GP];

    int tid = threadIdx.x;
    int lane = tid & 31, wid = tid >> 5;
    int warp_m = wid >> 2, warp_n = wid & 3;
    int row0 = blockIdx.x * 128;
    int n0 = blockIdx.y * 128;

    // per-thread chunk-load slots: 2 uint4 per matrix (A/B, hi/lo)
    int idx0 = tid, idx1 = tid + 256;
    int r0i = idx0 >> 2, q0 = idx0 & 3;
    int r1i = idx1 >> 2, q1 = idx1 & 3;

    float acc[4][4][4];
#pragma unroll
    for (int i = 0; i < 4; i++)
#pragma unroll
        for (int j = 0; j < 4; j++)
#pragma unroll
            for (int e = 0; e < 4; e++) acc[i][j][e] = 0.f;

    uint4 pf[8];
    // prefetch chunk 0
    {
        size_t a0 = (size_t)(row0 + r0i) * 256 + q0 * 8;
        size_t a1 = (size_t)(row0 + r1i) * 256 + q1 * 8;
        size_t b0 = (size_t)(n0 + r0i) * 256 + q0 * 8;
        size_t b1 = (size_t)(n0 + r1i) * 256 + q1 * 8;
        pf[0] = *(const uint4*)(g_ahi + a0); pf[1] = *(const uint4*)(g_ahi + a1);
        pf[2] = *(const uint4*)(g_alo + a0); pf[3] = *(const uint4*)(g_alo + a1);
        pf[4] = *(const uint4*)(g_whi + b0); pf[5] = *(const uint4*)(g_whi + b1);
        pf[6] = *(const uint4*)(g_wlo + b0); pf[7] = *(const uint4*)(g_wlo + b1);
    }

    uint32_t sAhi_b = smem_u32(sAhi), sAlo_b = smem_u32(sAlo);
    uint32_t sBhi_b = smem_u32(sBhi), sBlo_b = smem_u32(sBlo);

    // fragment smem byte offsets (within a matrix)
    uint32_t a_off[4], b_off[2];
#pragma unroll
    for (int mi = 0; mi < 4; mi++) {
        int row = warp_m * 64 + mi * 16 + (lane & 15);
        int col = ((lane >> 4) & 1) << 3;
        a_off[mi] = (uint32_t)(row * GP + col) * 2;
    }
#pragma unroll
    for (int p = 0; p < 2; p++) {
        int m = lane >> 3;
        int nrow = warp_n * 32 + p * 16 + ((m >> 1) << 3) + (lane & 7);
        int col = (m & 1) << 3;
        b_off[p] = (uint32_t)(nrow * GP + col) * 2;
    }
    uint32_t st0 = (uint32_t)(r0i * GP + q0 * 8) * 2;
    uint32_t st1 = (uint32_t)(r1i * GP + q1 * 8) * 2;

    for (int kc = 0; kc < 8; kc++) {
        // store prefetched chunk into smem
        *(uint4*)((char*)sAhi + st0) = pf[0]; *(uint4*)((char*)sAhi + st1) = pf[1];
        *(uint4*)((char*)sAlo + st0) = pf[2]; *(uint4*)((char*)sAlo + st1) = pf[3];
        *(uint4*)((char*)sBhi + st0) = pf[4]; *(uint4*)((char*)sBhi + st1) = pf[5];
        *(uint4*)((char*)sBlo + st0) = pf[6]; *(uint4*)((char*)sBlo + st1) = pf[7];
        __syncthreads();

        if (kc < 7) {
            int kn = (kc + 1) * 32;
            size_t a0 = (size_t)(row0 + r0i) * 256 + kn + q0 * 8;
            size_t a1 = (size_t)(row0 + r1i) * 256 + kn + q1 * 8;
            size_t b0 = (size_t)(n0 + r0i) * 256 + kn + q0 * 8;
            size_t b1 = (size_t)(n0 + r1i) * 256 + kn + q1 * 8;
            pf[0] = *(const uint4*)(g_ahi + a0); pf[1] = *(const uint4*)(g_ahi + a1);
            pf[2] = *(const uint4*)(g_alo + a0); pf[3] = *(const uint4*)(g_alo + a1);
            pf[4] = *(const uint4*)(g_whi + b0); pf[5] = *(const uint4*)(g_whi + b1);
            pf[6] = *(const uint4*)(g_wlo + b0); pf[7] = *(const uint4*)(g_wlo + b1);
        }

#pragma unroll
        for (int ks = 0; ks < 2; ks++) {
            uint32_t kb = (uint32_t)(ks * 16) * 2;  // byte offset for this k-step
            uint32_t ah[4][4], al[4][4], bh[2][4], bl[2][4];
#pragma unroll
            for (int mi = 0; mi < 4; mi++) {
                ldm4(sAhi_b + a_off[mi] + kb, ah[mi][0], ah[mi][1], ah[mi][2], ah[mi][3]);
                ldm4(sAlo_b + a_off[mi] + kb, al[mi][0], al[mi][1], al[mi][2], al[mi][3]);
            }
#pragma unroll
            for (int p = 0; p < 2; p++) {
                ldm4(sBhi_b + b_off[p] + kb, bh[p][0], bh[p][1], bh[p][2], bh[p][3]);
                ldm4(sBlo_b + b_off[p] + kb, bl[p][0], bl[p][1], bl[p][2], bl[p][3]);
            }
#pragma unroll
            for (int mi = 0; mi < 4; mi++) {
#pragma unroll
                for (int nj = 0; nj < 4; nj++) {
                    int p = nj >> 1, h = (nj & 1) << 1;
                    mma16816(acc[mi][nj], ah[mi], bh[p][h], bh[p][h + 1]);
                    mma16816(acc[mi][nj], ah[mi], bl[p][h], bl[p][h + 1]);
                    mma16816(acc[mi][nj], al[mi], bh[p][h], bh[p][h + 1]);
                }
            }
        }
        __syncthreads();
    }

    // epilogue: bias + scale, fp32 store
#pragma unroll
    for (int mi = 0; mi < 4; mi++) {
        int rbase = row0 + warp_m * 64 + mi * 16 + (lane >> 2);
#pragma unroll
        for (int nj = 0; nj < 4; nj++) {
            int c = n0 + warp_n * 32 + nj * 8 + ((lane & 3) << 1);
            float b0 = __ldg(bias + c), b1 = __ldg(bias + c + 1);
            float2 o0, o1;
            o0.x = (acc[mi][nj][0] + b0) * scale;
            o0.y = (acc[mi][nj][1] + b1) * scale;
            o1.x = (acc[mi][nj][2] + b0) * scale;
            o1.y = (acc[mi][nj][3] + b1) * scale;
            *(float2*)(outp + (size_t)rbase * 256 + c) = o0;
            *(float2*)(outp + (size_t)(rbase + 8) * 256 + c) = o1;
        }
    }
}

// ---------------- RoPE (in-place on g_q/g_k) + dt -> da/db ----------------
__device__ __forceinline__ float softplusf(float a) {
    return (a > 20.f) ? a : log1pf(expf(a));
}

__global__ __launch_bounds__(256) void rope_dt_kernel(
    const float* __restrict__ x, const float* __restrict__ sinp,
    const float* __restrict__ cosp, const float* __restrict__ dtw,
    const float* __restrict__ dtb, const float* __restrict__ Alog)
{
    int r = blockIdx.x;          // (b*64 + h)*64 + w
    int w = r & 63;
    int h = (r >> 6) & 63;
    int b = r >> 12;
    int c = threadIdx.x;
    int n = c >> 5, d = c & 31;

    float sv = sinp[(h * 64 + w) * 32 + d];
    float cv = cosp[(h * 64 + w) * 32 + d];

    float qv = g_q[r * 256 + c];
    float kv = g_k[r * 256 + c];
    float qp = __shfl_xor_sync(0xffffffffu, qv, 1);
    float kp = __shfl_xor_sync(0xffffffffu, kv, 1);
    float qr = (d & 1) ? qp : -qp;
    float kr = (d & 1) ? kp : -kp;
    g_q[r * 256 + c] = qv * cv + qr * sv;
    g_k[r * 256 + c] = kv * cv + kr * sv;

    float xv = x[r * 256 + c];
    float t0 = xv * dtw[d];
    float t1 = xv * dtw[32 + d];
#pragma unroll
    for (int off = 16; off; off >>= 1) {
        t0 += __shfl_down_sync(0xffffffffu, t0, off);
        t1 += __shfl_down_sync(0xffffffffu, t1, off);
    }
    if (d == 0) {
        float bias = dtb[n];
        float Aa = -expf(Alog[n]);
        float da = softplusf(t0 + bias) * Aa;
        float db = softplusf(t1 + bias) * Aa;
        g_da[((b * 64 + h) * 8 + n) * 64 + w] = da;
        g_db[((b * 64 + w) * 8 + n) * 64 + h] = db;
    }
}

// ---------------- LePE depthwise 5x5 conv ----------------
__global__ __launch_bounds__(256) void lepe_kernel(
    const float* __restrict__ lw, const float* __restrict__ lb)
{
    int r = blockIdx.x;
    int w = r & 63, h = (r >> 6) & 63, b = r >> 12;
    int c = threadIdx.x;
    float acc = lb[c];
#pragma unroll
    for (int ki = 0; ki < 5; ki++) {
        int hh = h + ki - 2;
        if ((unsigned)hh >= 64u) continue;
#pragma unroll
        for (int kj = 0; kj < 5; kj++) {
            int ww = w + kj - 2;
            if ((unsigned)ww >= 64u) continue;
            acc += __ldg(&g_v[((b * 64 + hh) * 64 + ww) * 256 + c]) * lw[(ki * 5 + kj) * 256 + c];
        }
    }
    g_lepe[r * 256 + c] = acc;
}

// ---------------- attention along W: qk_w (stored) + v_w ----------------
__global__ __launch_bounds__(256) void attn_w_kernel(void)
{
    int blk = blockIdx.x;                 // (b*64 + h)*8 + n
    int n = blk & 7;
    int h = (blk >> 3) & 63;
    int b = blk >> 9;
    __shared__ float qs[64][33];
    __shared__ float ks[64][33];
    __shared__ float S[64][65];
    __shared__ float cs[64];
    int tid = threadIdx.x;
    int qbase = ((b * 64 + h) * 64) * 256 + n * 32;

    for (int e = tid; e < 2048; e += 256) {
        int i = e >> 5, d = e & 31;
        qs[i][d] = g_q[qbase + i * 256 + d];
        ks[i][d] = g_k[qbase + i * 256 + d];
    }
    if (tid == 0) {
        float run = 0.f;
        const float* dap = g_da + blk * 64;
        for (int j = 0; j < 64; j++) { run += dap[j]; cs[j] = run; }
    }
    __syncthreads();

    int i0 = (tid >> 4) << 2;
    int j0 = (tid & 15) << 2;
    float s4[4][4];
#pragma unroll
    for (int a = 0; a < 4; a++)
#pragma unroll
        for (int c2 = 0; c2 < 4; c2++) s4[a][c2] = 0.f;
#pragma unroll 4
    for (int d = 0; d < 32; d++) {
        float qv[4], kv[4];
#pragma unroll
        for (int a = 0; a < 4; a++) qv[a] = qs[i0 + a][d];
#pragma unroll
        for (int a = 0; a < 4; a++) kv[a] = ks[j0 + a][d];
#pragma unroll
        for (int a = 0; a < 4; a++)
#pragma unroll
            for (int c2 = 0; c2 < 4; c2++) s4[a][c2] += qv[a] * kv[c2];
    }
#pragma unroll
    for (int a = 0; a < 4; a++) {
        int i = i0 + a;
#pragma unroll
        for (int c2 = 0; c2 < 4; c2++) {
            int j = j0 + c2;
            float diff = cs[i] - cs[j];
            S[i][j] = s4[a][c2] + ((i >= j) ? diff : -diff);
        }
    }
    __syncthreads();

    int wp = tid >> 5, lane = tid & 31;
    for (int rr = 0; rr < 8; rr++) {
        int i = wp * 8 + rr;
        float v0 = S[i][lane], v1 = S[i][lane + 32];
        float m = fmaxf(v0, v1);
#pragma unroll
        for (int off = 16; off; off >>= 1) m = fmaxf(m, __shfl_xor_sync(0xffffffffu, m, off));
        float e0 = expf(v0 - m), e1 = expf(v1 - m);
        float s = e0 + e1;
#pragma unroll
        for (int off = 16; off; off >>= 1) s += __shfl_xor_sync(0xffffffffu, s, off);
        float inv = 1.f / s;
        S[i][lane] = e0 * inv;
        S[i][lane + 32] = e1 * inv;
    }
    __syncthreads();

    float* qp = g_qkw + blk * 4096;
    for (int e = tid; e < 4096; e += 256) qp[e] = S[e >> 6][e & 63];

    for (int e = tid; e < 2048; e += 256) {
        int i = e >> 5, d = e & 31;
        qs[i][d] = g_v[qbase + i * 256 + d];
    }
    __syncthreads();

    int d = tid & 31;
    int ib = tid >> 5;
    float acc[8];
#pragma unroll
    for (int a = 0; a < 8; a++) acc[a] = 0.f;
    for (int j = 0; j < 64; j++) {
        float vv = qs[j][d];
#pragma unroll
        for (int a = 0; a < 8; a++) acc[a] += S[ib * 8 + a][j] * vv;
    }
    float* vwp = g_vw + blk * 2048;
#pragma unroll
    for (int a = 0; a < 8; a++) vwp[(ib * 8 + a) * 32 + d] = acc[a];
}

// ---- attention along H: qk_h in SMEM only; emits v_h2 and 0.5*out1 ----
__global__ __launch_bounds__(256) void attn_h_kernel(void)
{
    int blk = blockIdx.x;                 // (b*64 + x)*8 + n
    int n = blk & 7;
    int x = (blk >> 3) & 63;
    int b = blk >> 9;
    __shared__ float qs[64][33];
    __shared__ float ks[64][33];
    __shared__ float S[64][65];
    __shared__ float cs[64];
    int tid = threadIdx.x;
    int qbase = (b * 64 * 64 + x) * 256 + n * 32;

    for (int e = tid; e < 2048; e += 256) {
        int i = e >> 5, d = e & 31;
        qs[i][d] = g_q[qbase + i * 16384 + d];
        ks[i][d] = g_k[qbase + i * 16384 + d];
    }
    if (tid == 0) {
        float run = 0.f;
        const float* dbp = g_db + blk * 64;
        for (int j = 0; j < 64; j++) { run += dbp[j]; cs[j] = run; }
    }
    __syncthreads();

    int i0 = (tid >> 4) << 2;
    int j0 = (tid & 15) << 2;
    float s4[4][4];
#pragma unroll
    for (int a = 0; a < 4; a++)
#pragma unroll
        for (int c2 = 0; c2 < 4; c2++) s4[a][c2] = 0.f;
#pragma unroll 4
    for (int d = 0; d < 32; d++) {
        float qv[4], kv[4];
#pragma unroll
        for (int a = 0; a < 4; a++) qv[a] = qs[i0 + a][d];
#pragma unroll
        for (int a = 0; a < 4; a++) kv[a] = ks[j0 + a][d];
#pragma unroll
        for (int a = 0; a < 4; a++)
#pragma unroll
            for (int c2 = 0; c2 < 4; c2++) s4[a][c2] += qv[a] * kv[c2];
    }
#pragma unroll
    for (int a = 0; a < 4; a++) {
        int i = i0 + a;
#pragma unroll
        for (int c2 = 0; c2 < 4; c2++) {
            int j = j0 + c2;
            float diff = cs[i] - cs[j];
            S[i][j] = s4[a][c2] + ((i >= j) ? diff : -diff);
        }
    }
    __syncthreads();

    int wp = tid >> 5, lane = tid & 31;
    for (int rr = 0; rr < 8; rr++) {
        int i = wp * 8 + rr;
        float v0 = S[i][lane], v1 = S[i][lane + 32];
        float m = fmaxf(v0, v1);
#pragma unroll
        for (int off = 16; off; off >>= 1) m = fmaxf(m, __shfl_xor_sync(0xffffffffu, m, off));
        float e0 = expf(v0 - m), e1 = expf(v1 - m);
        float s = e0 + e1;
#pragma unroll
        for (int off = 16; off; off >>= 1) s += __shfl_xor_sync(0xffffffffu, s, off);
        float inv = 1.f / s;
        S[i][lane] = e0 * inv;
        S[i][lane + 32] = e1 * inv;
    }
    __syncthreads();

    for (int e = tid; e < 2048; e += 256) {
        int i = e >> 5, d = e & 31;
        qs[i][d] = g_v[qbase + i * 16384 + d];
        ks[i][d] = g_vw[((b * 64 + i) * 8 + n) * 2048 + x * 32 + d];
    }
    __syncthreads();

    int d = tid & 31;
    int ib = tid >> 5;
    float acc1[8], acc2[8];
#pragma unroll
    for (int a = 0; a < 8; a++) { acc1[a] = 0.f; acc2[a] = 0.f; }
    for (int j = 0; j < 64; j++) {
        float vv1 = qs[j][d];
        float vv2 = ks[j][d];
#pragma unroll
        for (int a = 0; a < 8; a++) {
            float p = S[ib * 8 + a][j];
            acc1[a] += p * vv1;
            acc2[a] += p * vv2;
        }
    }
    float* v2p = g_vh2 + blk * 2048;
#pragma unroll
    for (int a = 0; a < 8; a++) {
        int i = ib * 8 + a;
        v2p[i * 32 + d] = acc1[a];
        g_pre[((b * 64 + i) * 64 + x) * 256 + n * 32 + d] = 0.5f * acc2[a];
    }
}

// ---------------- out2: pre += 0.5*(qk_w @ v_h2) + lepe ----------------
__global__ __launch_bounds__(256) void out2_kernel(void)
{
    int blk = blockIdx.x;                 // (b*64 + y)*8 + n, y = h
    int n = blk & 7;
    int y = (blk >> 3) & 63;
    int b = blk >> 9;
    __shared__ float S[64][65];
    __shared__ float vs[64][33];
    int tid = threadIdx.x;

    const float* qp = g_qkw + blk * 4096;
    for (int e = tid; e < 4096; e += 256) S[e >> 6][e & 63] = qp[e];
    for (int e = tid; e < 2048; e += 256) {
        int j = e >> 5, d = e & 31;
        vs[j][d] = g_vh2[((b * 64 + j) * 8 + n) * 2048 + y * 32 + d];
    }
    __syncthreads();

    int d = tid & 31;
    int ib = tid >> 5;
    float acc[8];
#pragma unroll
    for (int a = 0; a < 8; a++) acc[a] = 0.f;
    for (int j = 0; j < 64; j++) {
        float vv = vs[j][d];
#pragma unroll
        for (int a = 0; a < 8; a++) acc[a] += S[ib * 8 + a][j] * vv;
    }
#pragma unroll
    for (int a = 0; a < 8; a++) {
        int i = ib * 8 + a;
        int addr = ((b * 64 + y) * 64 + i) * 256 + n * 32 + d;
        g_pre[addr] = g_pre[addr] + 0.5f * acc[a] + g_lepe[addr];
    }
}

// ---------------- launch ----------------
extern "C" void kernel_launch(void* const* d_in, const int* in_sizes, int n_in,
                              void* d_out, int out_size)
{
    const float* x    = (const float*)d_in[0];
    const float* sinp = (const float*)d_in[1];
    const float* cosp = (const float*)d_in[2];
    const float* Wq   = (const float*)d_in[3];
    const float* bq   = (const float*)d_in[4];
    const float* Wk   = (const float*)d_in[5];
    const float* bk   = (const float*)d_in[6];
    const float* Wv   = (const float*)d_in[7];
    const float* bv   = (const float*)d_in[8];
    const float* Wo   = (const float*)d_in[9];
    const float* bo   = (const float*)d_in[10];
    const float* lw   = (const float*)d_in[11];
    const float* lb   = (const float*)d_in[12];
    const float* dtw  = (const float*)d_in[13];
    const float* dtb  = (const float*)d_in[14];
    const float* Alog = (const float*)d_in[15];
    float* out = (float*)d_out;

    const float scaling = 0.17677669529663687f;   // 32^-0.5

    dim3 gg(NROW / 128, 2);
    int convA_blocks = (NROW * Cn) / (256 * 4);   // 16384
    int convW_blocks = (Cn * Cn) / (256 * 4);     // 64

    // split x into bf16 hi/lo once (shared by Q/K/V gemms)
    convA_kernel<<<convA_blocks, 256>>>(x, 0);

    convW_kernel<<<convW_blocks, 256>>>(Wq);
    gemm_mma_kernel<<<gg, 256>>>(bq, nullptr, 0, 1.0f);
    convW_kernel<<<convW_blocks, 256>>>(Wk);
    gemm_mma_kernel<<<gg, 256>>>(bk, nullptr, 1, scaling);
    convW_kernel<<<convW_blocks, 256>>>(Wv);
    gemm_mma_kernel<<<gg, 256>>>(bv, nullptr, 2, 1.0f);

    rope_dt_kernel<<<NROW, 256>>>(x, sinp, cosp, dtw, dtb, Alog);
    lepe_kernel<<<NROW, 256>>>(lw, lb);

    attn_w_kernel<<<Bn * Hn * Nn, 256>>>();
    attn_h_kernel<<<Bn * Wn * Nn, 256>>>();
    out2_kernel<<<Bn * Hn * Nn, 256>>>();

    convA_kernel<<<convA_blocks, 256>>>(nullptr, 1);
    convW_kernel<<<convW_blocks, 256>>>(Wo);
    gemm_mma_kernel<<<gg, 256>>>(bo, out, 3, 1.0f);
}